// round 1
// baseline (speedup 1.0000x reference)
#include <cuda_runtime.h>

#define NROWS 200000
#define NPAD  200064   /* 1563 * 128 */
#define CDIM  128
#define EPS   1e-5f

// Scratch: pre-BN activations for the 3 axes (padded to tile multiple so the
// GEMM can store unconditionally; padded rows never read, never counted).
__device__ float g_scratch[3L * NPAD * CDIM];
__device__ float g_sum[3 * CDIM];
__device__ float g_sumsq[3 * CDIM];
__device__ float g_scale[3 * CDIM];
__device__ float g_shift[3 * CDIM];

__global__ void zero_stats_kernel() {
    int t = blockIdx.x * blockDim.x + threadIdx.x;
    if (t < 3 * CDIM) { g_sum[t] = 0.f; g_sumsq[t] = 0.f; }
}

// One CTA computes a 128-row x 128-col tile of out_a = prev@W[a,0] + x@W[a,1] + next@W[a,2]
// 256 threads, 8x8 register microtile per thread (split as 2x 4-row / 4-col clusters).
__global__ __launch_bounds__(256, 2)
void gemm_bn_stats_kernel(const float* __restrict__ feat,
                          const int*   __restrict__ nb,
                          const float* __restrict__ W)
{
    const int  a  = blockIdx.y;
    const long i0 = (long)blockIdx.x * 128;
    const int  t  = threadIdx.x;
    const int  tm = t >> 4;       // 0..15  -> row clusters
    const int  tn = t & 15;       // 0..15  -> col clusters
    const int  lm = t >> 1;       // loader: row 0..127
    const int  lq = t & 1;        // loader: which half of the 16-wide k chunk

    __shared__ float As[16][132];       // [k][m], padded
    __shared__ float Bs[16][128];       // [k][n]
    __shared__ float s_sum[CDIM];
    __shared__ float s_sq[CDIM];

    if (t < CDIM) { s_sum[t] = 0.f; s_sq[t] = 0.f; }

    float acc[8][8];
    #pragma unroll
    for (int i = 0; i < 8; i++)
        #pragma unroll
        for (int j = 0; j < 8; j++) acc[i][j] = 0.f;

    const long gi = i0 + lm;

    #pragma unroll 1
    for (int s = 0; s < 3; s++) {
        // Gather index for this loader-thread's row. Sentinel NROWS => zero row.
        int ridx;
        if (gi >= NROWS)      ridx = NROWS;
        else if (s == 1)      ridx = (int)gi;
        else                  ridx = nb[((long)a * 2 + (s >> 1)) * NROWS + gi];
        const bool   rvalid = (ridx < NROWS);
        const float* arow   = feat + (long)ridx * CDIM;
        const float* wb     = W + (long)((a * 3 + s) * CDIM) * CDIM;

        #pragma unroll 1
        for (int k0 = 0; k0 < CDIM; k0 += 16) {
            __syncthreads();
            // Load A chunk (gathered rows), transposed into As[k][m]
            #pragma unroll
            for (int u = 0; u < 2; u++) {
                int kk = lq * 8 + u * 4;
                float4 v = make_float4(0.f, 0.f, 0.f, 0.f);
                if (rvalid) v = *(const float4*)(arow + k0 + kk);
                As[kk + 0][lm] = v.x; As[kk + 1][lm] = v.y;
                As[kk + 2][lm] = v.z; As[kk + 3][lm] = v.w;
            }
            // Load B chunk: W[a,s,k0+kk, :]
            #pragma unroll
            for (int u = 0; u < 2; u++) {
                int e  = t + u * 256;
                int kk = e >> 5;
                int n4 = (e & 31) << 2;
                *(float4*)&Bs[kk][n4] = *(const float4*)(wb + (k0 + kk) * CDIM + n4);
            }
            __syncthreads();
            #pragma unroll
            for (int k = 0; k < 16; k++) {
                float av[8], bv[8];
                *(float4*)&av[0] = *(const float4*)&As[k][tm * 4];
                *(float4*)&av[4] = *(const float4*)&As[k][64 + tm * 4];
                *(float4*)&bv[0] = *(const float4*)&Bs[k][tn * 4];
                *(float4*)&bv[4] = *(const float4*)&Bs[k][64 + tn * 4];
                #pragma unroll
                for (int i = 0; i < 8; i++)
                    #pragma unroll
                    for (int j = 0; j < 8; j++)
                        acc[i][j] += av[i] * bv[j];
            }
        }
    }

    // ---- store tile to scratch ----
    float* sc = g_scratch + (long)a * NPAD * CDIM;
    #pragma unroll
    for (int i = 0; i < 8; i++) {
        int  row = (i < 4) ? (tm * 4 + i) : (64 + tm * 4 + (i - 4));
        long gr  = i0 + row;
        float4 v0 = make_float4(acc[i][0], acc[i][1], acc[i][2], acc[i][3]);
        float4 v1 = make_float4(acc[i][4], acc[i][5], acc[i][6], acc[i][7]);
        *(float4*)(sc + gr * CDIM + tn * 4)       = v0;
        *(float4*)(sc + gr * CDIM + 64 + tn * 4)  = v1;
    }

    // ---- per-column partial stats (valid rows only) ----
    #pragma unroll
    for (int j = 0; j < 8; j++) {
        int col = (j < 4) ? (tn * 4 + j) : (64 + tn * 4 + (j - 4));
        float ps = 0.f, pq = 0.f;
        #pragma unroll
        for (int i = 0; i < 8; i++) {
            int row = (i < 4) ? (tm * 4 + i) : (64 + tm * 4 + (i - 4));
            if (i0 + row < NROWS) { float v = acc[i][j]; ps += v; pq += v * v; }
        }
        atomicAdd(&s_sum[col], ps);
        atomicAdd(&s_sq[col],  pq);
    }
    __syncthreads();
    if (t < CDIM) {
        atomicAdd(&g_sum[a * CDIM + t],   s_sum[t]);
        atomicAdd(&g_sumsq[a * CDIM + t], s_sq[t]);
    }
}

__global__ void finalize_kernel(const float* __restrict__ gamma,
                                const float* __restrict__ beta)
{
    int t = blockIdx.x * blockDim.x + threadIdx.x;
    if (t >= 3 * CDIM) return;
    float inv_n = 1.0f / (float)NROWS;
    float mu  = g_sum[t] * inv_n;
    float var = g_sumsq[t] * inv_n - mu * mu;
    float sc  = gamma[t] * rsqrtf(var + EPS);
    g_scale[t] = sc;
    g_shift[t] = beta[t] - mu * sc;
}

__global__ __launch_bounds__(256)
void epilogue_kernel(const float* __restrict__ feat, float* __restrict__ out)
{
    long gid = (long)blockIdx.x * blockDim.x + threadIdx.x;   // one float4 each
    if (gid >= (long)NROWS * (CDIM / 4)) return;
    long i  = gid >> 5;
    int  c4 = ((int)gid & 31) << 2;

    float4 f = *(const float4*)(feat + i * CDIM + c4);
    float r0 = 0.f, r1 = 0.f, r2 = 0.f, r3 = 0.f;
    #pragma unroll
    for (int a = 0; a < 3; a++) {
        float4 v  = *(const float4*)(g_scratch + ((long)a * NPAD + i) * CDIM + c4);
        float4 sc = *(const float4*)(g_scale + a * CDIM + c4);
        float4 sh = *(const float4*)(g_shift + a * CDIM + c4);
        r0 += 1.f / (1.f + __expf(-(v.x * sc.x + sh.x)));
        r1 += 1.f / (1.f + __expf(-(v.y * sc.y + sh.y)));
        r2 += 1.f / (1.f + __expf(-(v.z * sc.z + sh.z)));
        r3 += 1.f / (1.f + __expf(-(v.w * sc.w + sh.w)));
    }
    float4 o = make_float4(r0 * f.x, r1 * f.y, r2 * f.z, r3 * f.w);
    *(float4*)(out + i * CDIM + c4) = o;
}

extern "C" void kernel_launch(void* const* d_in, const int* in_sizes, int n_in,
                              void* d_out, int out_size)
{
    const float* feat  = (const float*)d_in[0];
    const int*   nb    = (const int*)  d_in[1];
    const float* W     = (const float*)d_in[2];
    const float* gamma = (const float*)d_in[3];
    const float* beta  = (const float*)d_in[4];
    float*       out   = (float*)d_out;

    zero_stats_kernel<<<2, 256>>>();
    dim3 g(NPAD / 128, 3);
    gemm_bn_stats_kernel<<<g, 256>>>(feat, nb, W);
    finalize_kernel<<<2, 256>>>(gamma, beta);
    epilogue_kernel<<<25000, 256>>>(feat, out);
}

// round 4
// speedup vs baseline: 2.3326x; 2.3326x over previous
#include <cuda_runtime.h>
#include <cstdint>

#define NROWS 200000
#define NPAD  200064   /* 1563 * 128 */
#define CDIM  128
#define EPS   1e-5f

__device__ float g_scratch[3L * NPAD * CDIM];
__device__ float g_sum[3 * CDIM];
__device__ float g_sumsq[3 * CDIM];
__device__ float g_scale[3 * CDIM];
__device__ float g_shift[3 * CDIM];

__device__ __forceinline__ uint32_t smem_u32(const void* p) {
    uint32_t a;
    asm("{ .reg .u64 t; cvta.to.shared.u64 t, %1; cvt.u32.u64 %0, t; }" : "=r"(a) : "l"(p));
    return a;
}
__device__ __forceinline__ uint32_t f2tf32(float f) {
    uint32_t u;
    asm("cvt.rna.tf32.f32 %0, %1;" : "=r"(u) : "f"(f));
    return u;
}
__device__ __forceinline__ float lds_f32(uint32_t addr) {
    float v;
    asm volatile("ld.shared.f32 %0, [%1];" : "=f"(v) : "r"(addr));
    return v;
}
#define CP_ASYNC16(dst, src, sz) \
    asm volatile("cp.async.cg.shared.global [%0], [%1], 16, %2;" \
                 :: "r"(dst), "l"(src), "r"(sz) : "memory")
#define CP_COMMIT()  asm volatile("cp.async.commit_group;" ::: "memory")
#define CP_WAIT2()   asm volatile("cp.async.wait_group 2;" ::: "memory")

#define MMA_TF32(c, au, bu)                                                     \
    asm volatile("mma.sync.aligned.m16n8k8.row.col.f32.tf32.tf32.f32 "          \
        "{%0,%1,%2,%3}, {%4,%5,%6,%7}, {%8,%9}, {%0,%1,%2,%3};"                 \
        : "+f"((c)[0]), "+f"((c)[1]), "+f"((c)[2]), "+f"((c)[3])                \
        : "r"((au)[0]), "r"((au)[1]), "r"((au)[2]), "r"((au)[3]),               \
          "r"((bu)[0]), "r"((bu)[1]))

// SMEM geometry (bytes): A tile [128 rows x 32 k] padded to 36 floats/row,
// B tile [32 k x 128 n] padded to 136 floats/row. 3 pipeline buffers.
#define A_ROW_B   144u          /* 36 floats */
#define A_SZ      18432u        /* 128*144  */
#define B_ROW_B   544u          /* 136 floats */
#define B_SZ      17408u        /* 32*544   */
#define BUF_SZ    35840u
#define SMEM_DYN  107520u       /* 3 * BUF_SZ */

__global__ void zero_stats_kernel() {
    int t = blockIdx.x * blockDim.x + threadIdx.x;
    if (t < 3 * CDIM) { g_sum[t] = 0.f; g_sumsq[t] = 0.f; }
}

// One CTA: 128-row x 128-col tile of out_a for axis a = blockIdx.y.
// 8 warps: wm = wid&1 (two 64-row bands), wn = wid>>1 (four 32-col bands).
// Warp tile 64x32 = 4x4 mma(m16n8k8) tiles, tf32, fp32 accumulate.
__global__ __launch_bounds__(256)
void gemm_bn_stats_kernel(const float* __restrict__ feat,
                          const int*   __restrict__ nb,
                          const float* __restrict__ W)
{
    extern __shared__ char smem[];
    __shared__ int   s_idx[2][128];
    __shared__ float s_sum[CDIM];
    __shared__ float s_sq[CDIM];

    const int t    = threadIdx.x;
    const int lane = t & 31;
    const int wid  = t >> 5;
    const int grp  = lane >> 2;
    const int tg   = lane & 3;
    const int m_base = (wid & 1) * 64;
    const int n_base = (wid >> 1) * 32;
    const int a    = blockIdx.y;
    const long i0  = (long)blockIdx.x * 128;
    const uint32_t sbase = smem_u32(smem);

    if (t < CDIM) { s_sum[t] = 0.f; s_sq[t] = 0.f; }
    {   // precompute gather indices for prev (si=0) / next (si=1)
        int si = t >> 7, r = t & 127;
        long gi = i0 + r;
        int v = NROWS;
        if (gi < NROWS) v = nb[((long)a * 2 + si) * NROWS + gi];
        s_idx[si][r] = v;
    }
    __syncthreads();

    auto issue = [&](int st) {
        const int s = st >> 2, kc = st & 3, buf = st % 3;
        const uint32_t Ab = sbase + (uint32_t)buf * BUF_SZ;
        const uint32_t Bb = Ab + A_SZ;
        // A: gathered rows, 128 rows x 32 floats, zfill for sentinel rows
        #pragma unroll
        for (int it = 0; it < 4; it++) {
            int f4  = t + it * 256;
            int row = f4 >> 3, kq = f4 & 7;
            long gi = i0 + row;
            int ridx;
            if (s == 1) ridx = (gi < NROWS) ? (int)gi : NROWS;
            else        ridx = s_idx[s >> 1][row];
            const bool   ok  = (ridx < NROWS);
            const float* src = feat + (ok ? ((long)ridx * CDIM + kc * 32 + kq * 4) : 0);
            uint32_t sz  = ok ? 16u : 0u;
            uint32_t dst = Ab + (uint32_t)row * A_ROW_B + (uint32_t)kq * 16u;
            CP_ASYNC16(dst, src, sz);
        }
        // B: W[a][s][kc*32 + kk][n], row-major in n
        const float* wsrc = W + ((long)(a * 3 + s) * CDIM + kc * 32) * CDIM;
        #pragma unroll
        for (int it = 0; it < 4; it++) {
            int f4 = t + it * 256;
            int kk = f4 >> 5, n4 = (f4 & 31) << 2;
            uint32_t dst = Bb + (uint32_t)kk * B_ROW_B + (uint32_t)n4 * 4u;
            CP_ASYNC16(dst, wsrc + (long)kk * CDIM + n4, 16u);
        }
    };

    issue(0); CP_COMMIT();
    issue(1); CP_COMMIT();

    float acc[4][4][4];
    #pragma unroll
    for (int i = 0; i < 4; i++)
        #pragma unroll
        for (int j = 0; j < 4; j++)
            #pragma unroll
            for (int q = 0; q < 4; q++) acc[i][j][q] = 0.f;

    const uint32_t aoff = (uint32_t)((m_base + grp) * 144 + tg * 4);
    const uint32_t boff = (uint32_t)(tg * 544 + (n_base + grp) * 4);

    #pragma unroll 1
    for (int st = 0; st < 12; st++) {
        if (st + 2 < 12) issue(st + 2);
        CP_COMMIT();
        CP_WAIT2();
        __syncthreads();

        const int buf = st % 3;
        const uint32_t Ab = sbase + (uint32_t)buf * BUF_SZ + aoff;
        const uint32_t Bb = sbase + (uint32_t)buf * BUF_SZ + A_SZ + boff;

        #pragma unroll
        for (int k = 0; k < 4; k++) {           // k-step of 8 within the 32-chunk
            const uint32_t ak = Ab + (uint32_t)k * 32u;     // +8 floats
            const uint32_t bk = Bb + (uint32_t)k * 4352u;   // +8 B-rows
            uint32_t af[4][4];
            #pragma unroll
            for (int mt = 0; mt < 4; mt++) {
                uint32_t base = ak + (uint32_t)mt * 2304u;  // +16 A-rows
                af[mt][0] = f2tf32(lds_f32(base));
                af[mt][1] = f2tf32(lds_f32(base + 1152u));  // +8 rows
                af[mt][2] = f2tf32(lds_f32(base + 16u));    // +4 k
                af[mt][3] = f2tf32(lds_f32(base + 1168u));
            }
            uint32_t bu[4][2];
            #pragma unroll
            for (int nt = 0; nt < 4; nt++) {
                uint32_t base = bk + (uint32_t)nt * 32u;    // +8 cols
                bu[nt][0] = f2tf32(lds_f32(base));
                bu[nt][1] = f2tf32(lds_f32(base + 2176u));  // +4 B-rows
            }
            #pragma unroll
            for (int mt = 0; mt < 4; mt++)
                #pragma unroll
                for (int nt = 0; nt < 4; nt++)
                    MMA_TF32(acc[mt][nt], af[mt], bu[nt]);
        }
        __syncthreads();
    }

    // ---- store tile to scratch + per-column stats ----
    const int vr = (int)(((NROWS - i0) < 128) ? (NROWS - i0) : 128);
    float* sc = g_scratch + ((long)a * NPAD + i0) * CDIM;

    #pragma unroll
    for (int nt = 0; nt < 4; nt++) {
        const int c_lo = n_base + nt * 8 + tg * 2;
        float sA = 0.f, qA = 0.f, sB = 0.f, qB = 0.f;
        #pragma unroll
        for (int mt = 0; mt < 4; mt++) {
            const int r0 = m_base + mt * 16 + grp;
            const int r1 = r0 + 8;
            float2 v0 = make_float2(acc[mt][nt][0], acc[mt][nt][1]);
            float2 v1 = make_float2(acc[mt][nt][2], acc[mt][nt][3]);
            *(float2*)(sc + (long)r0 * CDIM + c_lo) = v0;
            *(float2*)(sc + (long)r1 * CDIM + c_lo) = v1;
            if (r0 < vr) { sA += v0.x; qA += v0.x * v0.x; sB += v0.y; qB += v0.y * v0.y; }
            if (r1 < vr) { sA += v1.x; qA += v1.x * v1.x; sB += v1.y; qB += v1.y * v1.y; }
        }
        atomicAdd(&s_sum[c_lo],     sA); atomicAdd(&s_sq[c_lo],     qA);
        atomicAdd(&s_sum[c_lo + 1], sB); atomicAdd(&s_sq[c_lo + 1], qB);
    }
    __syncthreads();
    if (t < CDIM) {
        atomicAdd(&g_sum[a * CDIM + t],   s_sum[t]);
        atomicAdd(&g_sumsq[a * CDIM + t], s_sq[t]);
    }
}

__global__ void finalize_kernel(const float* __restrict__ gamma,
                                const float* __restrict__ beta)
{
    int t = blockIdx.x * blockDim.x + threadIdx.x;
    if (t >= 3 * CDIM) return;
    float inv_n = 1.0f / (float)NROWS;
    float mu  = g_sum[t] * inv_n;
    float var = g_sumsq[t] * inv_n - mu * mu;
    float sc  = gamma[t] * rsqrtf(var + EPS);
    g_scale[t] = sc;
    g_shift[t] = beta[t] - mu * sc;
}

__global__ __launch_bounds__(256)
void epilogue_kernel(const float* __restrict__ feat, float* __restrict__ out)
{
    long gid = (long)blockIdx.x * blockDim.x + threadIdx.x;   // one float4 each
    if (gid >= (long)NROWS * (CDIM / 4)) return;
    long i  = gid >> 5;
    int  c4 = ((int)gid & 31) << 2;

    float4 f = *(const float4*)(feat + i * CDIM + c4);
    float r0 = 0.f, r1 = 0.f, r2 = 0.f, r3 = 0.f;
    #pragma unroll
    for (int a = 0; a < 3; a++) {
        float4 v  = *(const float4*)(g_scratch + ((long)a * NPAD + i) * CDIM + c4);
        float4 sc = *(const float4*)(g_scale + a * CDIM + c4);
        float4 sh = *(const float4*)(g_shift + a * CDIM + c4);
        r0 += 1.f / (1.f + __expf(-(v.x * sc.x + sh.x)));
        r1 += 1.f / (1.f + __expf(-(v.y * sc.y + sh.y)));
        r2 += 1.f / (1.f + __expf(-(v.z * sc.z + sh.z)));
        r3 += 1.f / (1.f + __expf(-(v.w * sc.w + sh.w)));
    }
    float4 o = make_float4(r0 * f.x, r1 * f.y, r2 * f.z, r3 * f.w);
    *(float4*)(out + i * CDIM + c4) = o;
}

extern "C" void kernel_launch(void* const* d_in, const int* in_sizes, int n_in,
                              void* d_out, int out_size)
{
    const float* feat  = (const float*)d_in[0];
    const int*   nb    = (const int*)  d_in[1];
    const float* W     = (const float*)d_in[2];
    const float* gamma = (const float*)d_in[3];
    const float* beta  = (const float*)d_in[4];
    float*       out   = (float*)d_out;

    cudaFuncSetAttribute(gemm_bn_stats_kernel,
                         cudaFuncAttributeMaxDynamicSharedMemorySize, SMEM_DYN);

    zero_stats_kernel<<<2, 256>>>();
    dim3 g(NPAD / 128, 3);
    gemm_bn_stats_kernel<<<g, 256, SMEM_DYN>>>(feat, nb, W);
    finalize_kernel<<<2, 256>>>(gamma, beta);
    epilogue_kernel<<<25000, 256>>>(feat, out);
}

// round 7
// speedup vs baseline: 2.3552x; 1.0097x over previous
#include <cuda_runtime.h>
#include <cstdint>

#define NROWS 200000
#define NPAD  200064   /* 1563 * 128 */
#define CDIM  128
#define EPS   1e-5f

__device__ float g_scratch[3L * NPAD * CDIM];
__device__ float g_sum[3 * CDIM];
__device__ float g_sumsq[3 * CDIM];
__device__ float g_scale[3 * CDIM];
__device__ float g_shift[3 * CDIM];

__device__ __forceinline__ uint32_t smem_u32(const void* p) {
    uint32_t a;
    asm("{ .reg .u64 t; cvta.to.shared.u64 t, %1; cvt.u32.u64 %0, t; }" : "=r"(a) : "l"(p));
    return a;
}
__device__ __forceinline__ uint32_t f2tf32(float f) {
    uint32_t u;
    asm("cvt.rna.tf32.f32 %0, %1;" : "=r"(u) : "f"(f));
    return u;
}
__device__ __forceinline__ float lds_f32(uint32_t addr) {
    float v;
    asm volatile("ld.shared.f32 %0, [%1];" : "=f"(v) : "r"(addr));
    return v;
}
#define CP_ASYNC16(dst, src, sz) \
    asm volatile("cp.async.cg.shared.global [%0], [%1], 16, %2;" \
                 :: "r"(dst), "l"(src), "r"(sz) : "memory")
#define CP_COMMIT()  asm volatile("cp.async.commit_group;" ::: "memory")
#define CP_WAIT1()   asm volatile("cp.async.wait_group 1;" ::: "memory")

#define MMA_TF32(c, au, bu)                                                     \
    asm volatile("mma.sync.aligned.m16n8k8.row.col.f32.tf32.tf32.f32 "          \
        "{%0,%1,%2,%3}, {%4,%5,%6,%7}, {%8,%9}, {%0,%1,%2,%3};"                 \
        : "+f"((c)[0]), "+f"((c)[1]), "+f"((c)[2]), "+f"((c)[3])                \
        : "r"((au)[0]), "r"((au)[1]), "r"((au)[2]), "r"((au)[3]),               \
          "r"((bu)[0]), "r"((bu)[1]))

// SMEM geometry (bytes): A tile [128 rows x 32 k] padded to 36 floats/row,
// B tile [32 k x 128 n] padded to 136 floats/row. 2 pipeline buffers -> occ 2.
#define A_ROW_B   144u          /* 36 floats */
#define A_SZ      18432u        /* 128*144  */
#define B_ROW_B   544u          /* 136 floats */
#define B_SZ      17408u        /* 32*544   */
#define BUF_SZ    35840u
#define SMEM_DYN  71680u        /* 2 * BUF_SZ */

__global__ void zero_stats_kernel() {
    int t = blockIdx.x * blockDim.x + threadIdx.x;
    if (t < 3 * CDIM) { g_sum[t] = 0.f; g_sumsq[t] = 0.f; }
}

// One CTA: 128-row x 128-col tile of out_a for axis a = blockIdx.y.
// 8 warps: wm = wid&1 (two 64-row bands), wn = wid>>1 (four 32-col bands).
// Warp tile 64x32 = 4x4 mma(m16n8k8) tiles, tf32, fp32 accumulate.
__global__ __launch_bounds__(256, 2)
void gemm_bn_stats_kernel(const float* __restrict__ feat,
                          const int*   __restrict__ nb,
                          const float* __restrict__ W)
{
    extern __shared__ char smem[];
    __shared__ int   s_idx[2][128];
    __shared__ float s_sum[CDIM];
    __shared__ float s_sq[CDIM];

    const int t    = threadIdx.x;
    const int lane = t & 31;
    const int wid  = t >> 5;
    const int grp  = lane >> 2;
    const int tg   = lane & 3;
    const int m_base = (wid & 1) * 64;
    const int n_base = (wid >> 1) * 32;
    const int a    = blockIdx.y;
    const long i0  = (long)blockIdx.x * 128;
    const uint32_t sbase = smem_u32(smem);

    if (t < CDIM) { s_sum[t] = 0.f; s_sq[t] = 0.f; }
    {   // precompute gather indices for prev (si=0) / next (si=1)
        int si = t >> 7, r = t & 127;
        long gi = i0 + r;
        int v = NROWS;
        if (gi < NROWS) v = nb[((long)a * 2 + si) * NROWS + gi];
        s_idx[si][r] = v;
    }
    __syncthreads();

    auto issue = [&](int st) {
        const int s = st >> 2, kc = st & 3, buf = st & 1;
        const uint32_t Ab = sbase + (uint32_t)buf * BUF_SZ;
        const uint32_t Bb = Ab + A_SZ;
        // A: gathered rows, 128 rows x 32 floats, zfill for sentinel rows
        #pragma unroll
        for (int it = 0; it < 4; it++) {
            int f4  = t + it * 256;
            int row = f4 >> 3, kq = f4 & 7;
            long gi = i0 + row;
            int ridx;
            if (s == 1) ridx = (gi < NROWS) ? (int)gi : NROWS;
            else        ridx = s_idx[s >> 1][row];
            const bool   ok  = (ridx < NROWS);
            const float* src = feat + (ok ? ((long)ridx * CDIM + kc * 32 + kq * 4) : 0);
            uint32_t sz  = ok ? 16u : 0u;
            uint32_t dst = Ab + (uint32_t)row * A_ROW_B + (uint32_t)kq * 16u;
            CP_ASYNC16(dst, src, sz);
        }
        // B: W[a][s][kc*32 + kk][n], row-major in n
        const float* wsrc = W + ((long)(a * 3 + s) * CDIM + kc * 32) * CDIM;
        #pragma unroll
        for (int it = 0; it < 4; it++) {
            int f4 = t + it * 256;
            int kk = f4 >> 5, n4 = (f4 & 31) << 2;
            uint32_t dst = Bb + (uint32_t)kk * B_ROW_B + (uint32_t)n4 * 4u;
            CP_ASYNC16(dst, wsrc + (long)kk * CDIM + n4, 16u);
        }
    };

    issue(0); CP_COMMIT();
    issue(1); CP_COMMIT();

    float acc[4][4][4];
    #pragma unroll
    for (int i = 0; i < 4; i++)
        #pragma unroll
        for (int j = 0; j < 4; j++)
            #pragma unroll
            for (int q = 0; q < 4; q++) acc[i][j][q] = 0.f;

    const uint32_t aoff = (uint32_t)((m_base + grp) * 144 + tg * 4);
    const uint32_t boff = (uint32_t)(tg * 544 + (n_base + grp) * 4);

    #pragma unroll 1
    for (int st = 0; st < 12; st++) {
        // Wait until group #st is complete (committed groups beyond it: <=1).
        CP_WAIT1();
        __syncthreads();

        const int buf = st & 1;
        const uint32_t Ab = sbase + (uint32_t)buf * BUF_SZ + aoff;
        const uint32_t Bb = sbase + (uint32_t)buf * BUF_SZ + A_SZ + boff;

        #pragma unroll
        for (int k = 0; k < 4; k++) {           // k-step of 8 within the 32-chunk
            const uint32_t ak = Ab + (uint32_t)k * 32u;     // +8 floats
            const uint32_t bk = Bb + (uint32_t)k * 4352u;   // +8 B-rows
            uint32_t af[4][4];
            #pragma unroll
            for (int mt = 0; mt < 4; mt++) {
                uint32_t base = ak + (uint32_t)mt * 2304u;  // +16 A-rows
                af[mt][0] = f2tf32(lds_f32(base));
                af[mt][1] = f2tf32(lds_f32(base + 1152u));  // +8 rows
                af[mt][2] = f2tf32(lds_f32(base + 16u));    // +4 k
                af[mt][3] = f2tf32(lds_f32(base + 1168u));
            }
            uint32_t bu[4][2];
            #pragma unroll
            for (int nt = 0; nt < 4; nt++) {
                uint32_t base = bk + (uint32_t)nt * 32u;    // +8 cols
                bu[nt][0] = f2tf32(lds_f32(base));
                bu[nt][1] = f2tf32(lds_f32(base + 2176u));  // +4 B-rows
            }
            #pragma unroll
            for (int mt = 0; mt < 4; mt++)
                #pragma unroll
                for (int nt = 0; nt < 4; nt++)
                    MMA_TF32(acc[mt][nt], af[mt], bu[nt]);
        }
        __syncthreads();   // all warps done reading buf before refilling it
        if (st + 2 < 12) issue(st + 2);
        CP_COMMIT();       // unconditional: keeps group numbering for CP_WAIT1
    }

    // ---- store tile to scratch + per-column stats ----
    const int vr = (int)(((NROWS - i0) < 128) ? (NROWS - i0) : 128);
    float* sc = g_scratch + ((long)a * NPAD + i0) * CDIM;

    #pragma unroll
    for (int nt = 0; nt < 4; nt++) {
        const int c_lo = n_base + nt * 8 + tg * 2;
        float sA = 0.f, qA = 0.f, sB = 0.f, qB = 0.f;
        #pragma unroll
        for (int mt = 0; mt < 4; mt++) {
            const int r0 = m_base + mt * 16 + grp;
            const int r1 = r0 + 8;
            float2 v0 = make_float2(acc[mt][nt][0], acc[mt][nt][1]);
            float2 v1 = make_float2(acc[mt][nt][2], acc[mt][nt][3]);
            *(float2*)(sc + (long)r0 * CDIM + c_lo) = v0;
            *(float2*)(sc + (long)r1 * CDIM + c_lo) = v1;
            if (r0 < vr) { sA += v0.x; qA += v0.x * v0.x; sB += v0.y; qB += v0.y * v0.y; }
            if (r1 < vr) { sA += v1.x; qA += v1.x * v1.x; sB += v1.y; qB += v1.y * v1.y; }
        }
        atomicAdd(&s_sum[c_lo],     sA); atomicAdd(&s_sq[c_lo],     qA);
        atomicAdd(&s_sum[c_lo + 1], sB); atomicAdd(&s_sq[c_lo + 1], qB);
    }
    __syncthreads();
    if (t < CDIM) {
        atomicAdd(&g_sum[a * CDIM + t],   s_sum[t]);
        atomicAdd(&g_sumsq[a * CDIM + t], s_sq[t]);
    }
}

__global__ void finalize_kernel(const float* __restrict__ gamma,
                                const float* __restrict__ beta)
{
    int t = blockIdx.x * blockDim.x + threadIdx.x;
    if (t >= 3 * CDIM) return;
    float inv_n = 1.0f / (float)NROWS;
    float mu  = g_sum[t] * inv_n;
    float var = g_sumsq[t] * inv_n - mu * mu;
    float sc  = gamma[t] * rsqrtf(var + EPS);
    g_scale[t] = sc;
    g_shift[t] = beta[t] - mu * sc;
}

__global__ __launch_bounds__(256)
void epilogue_kernel(const float* __restrict__ feat, float* __restrict__ out)
{
    long gid = (long)blockIdx.x * blockDim.x + threadIdx.x;   // one float4 each
    if (gid >= (long)NROWS * (CDIM / 4)) return;
    long i  = gid >> 5;
    int  c4 = ((int)gid & 31) << 2;

    float4 f = *(const float4*)(feat + i * CDIM + c4);
    float r0 = 0.f, r1 = 0.f, r2 = 0.f, r3 = 0.f;
    #pragma unroll
    for (int a = 0; a < 3; a++) {
        float4 v  = *(const float4*)(g_scratch + ((long)a * NPAD + i) * CDIM + c4);
        float4 sc = *(const float4*)(g_scale + a * CDIM + c4);
        float4 sh = *(const float4*)(g_shift + a * CDIM + c4);
        r0 += 1.f / (1.f + __expf(-(v.x * sc.x + sh.x)));
        r1 += 1.f / (1.f + __expf(-(v.y * sc.y + sh.y)));
        r2 += 1.f / (1.f + __expf(-(v.z * sc.z + sh.z)));
        r3 += 1.f / (1.f + __expf(-(v.w * sc.w + sh.w)));
    }
    float4 o = make_float4(r0 * f.x, r1 * f.y, r2 * f.z, r3 * f.w);
    *(float4*)(out + i * CDIM + c4) = o;
}

extern "C" void kernel_launch(void* const* d_in, const int* in_sizes, int n_in,
                              void* d_out, int out_size)
{
    const float* feat  = (const float*)d_in[0];
    const int*   nb    = (const int*)  d_in[1];
    const float* W     = (const float*)d_in[2];
    const float* gamma = (const float*)d_in[3];
    const float* beta  = (const float*)d_in[4];
    float*       out   = (float*)d_out;

    cudaFuncSetAttribute(gemm_bn_stats_kernel,
                         cudaFuncAttributeMaxDynamicSharedMemorySize, SMEM_DYN);

    zero_stats_kernel<<<2, 256>>>();
    dim3 g(NPAD / 128, 3);
    gemm_bn_stats_kernel<<<g, 256, SMEM_DYN>>>(feat, nb, W);
    finalize_kernel<<<2, 256>>>(gamma, beta);
    epilogue_kernel<<<25000, 256>>>(feat, out);
}

// round 8
// speedup vs baseline: 2.3904x; 1.0149x over previous
#include <cuda_runtime.h>
#include <cuda_fp16.h>
#include <cstdint>

#define NROWS 200000
#define NPAD  200064   /* 1563 * 128 */
#define CDIM  128
#define EPS   1e-5f

__device__ float g_scratch[3L * NPAD * CDIM];
__device__ float g_sum[3 * CDIM];
__device__ float g_sumsq[3 * CDIM];
__device__ float g_scale[3 * CDIM];
__device__ float g_shift[3 * CDIM];

__device__ __forceinline__ uint32_t smem_u32(const void* p) {
    uint32_t a;
    asm("{ .reg .u64 t; cvta.to.shared.u64 t, %1; cvt.u32.u64 %0, t; }" : "=r"(a) : "l"(p));
    return a;
}
__device__ __forceinline__ uint32_t pack_h2(float lo, float hi) {
    __half2 h = __floats2half2_rn(lo, hi);
    return *reinterpret_cast<uint32_t*>(&h);
}

#define STS128(addr, r0, r1, r2, r3) \
    asm volatile("st.shared.v4.b32 [%0], {%1,%2,%3,%4};" \
                 :: "r"(addr), "r"(r0), "r"(r1), "r"(r2), "r"(r3) : "memory")

#define LDSM_X4(r, addr) \
    asm volatile("ldmatrix.sync.aligned.m8n8.x4.shared.b16 {%0,%1,%2,%3}, [%4];" \
                 : "=r"((r)[0]), "=r"((r)[1]), "=r"((r)[2]), "=r"((r)[3]) : "r"(addr))
#define LDSM_X4_T(r, addr) \
    asm volatile("ldmatrix.sync.aligned.m8n8.x4.trans.shared.b16 {%0,%1,%2,%3}, [%4];" \
                 : "=r"((r)[0]), "=r"((r)[1]), "=r"((r)[2]), "=r"((r)[3]) : "r"(addr))

#define MMA_F16(c, au, bu)                                                      \
    asm volatile("mma.sync.aligned.m16n8k16.row.col.f32.f16.f16.f32 "           \
        "{%0,%1,%2,%3}, {%4,%5,%6,%7}, {%8,%9}, {%0,%1,%2,%3};"                 \
        : "+f"((c)[0]), "+f"((c)[1]), "+f"((c)[2]), "+f"((c)[3])                \
        : "r"((au)[0]), "r"((au)[1]), "r"((au)[2]), "r"((au)[3]),               \
          "r"((bu)[0]), "r"((bu)[1]))

// fp16 SMEM tiles per stage: A [128 rows x 32 k] = 64 B/row (4 x 16B chunks,
// chunk ^= (row>>1)&3). B [32 k x 128 n] = 256 B/row (16 chunks, chunk ^= k&7).
#define A_TILE    8192u
#define B_TILE    8192u
#define BUF_SZ    16384u
#define SMEM_DYN  32768u   /* 2 buffers */

__global__ void zero_stats_kernel() {
    int t = blockIdx.x * blockDim.x + threadIdx.x;
    if (t < 3 * CDIM) { g_sum[t] = 0.f; g_sumsq[t] = 0.f; }
}

// One CTA: 128-row x 128-col tile of out_a for axis a = blockIdx.y.
// 8 warps: wm = wid&1 (two 64-row bands), wn = wid>>1 (four 32-col bands).
// Warp tile 64x32 = 4x4 mma(m16n8k16) tiles, fp16 in, fp32 accumulate.
__global__ __launch_bounds__(256, 2)
void gemm_bn_stats_kernel(const float* __restrict__ feat,
                          const int*   __restrict__ nb,
                          const float* __restrict__ W)
{
    extern __shared__ char smem[];
    __shared__ int   s_idx[2][128];
    __shared__ float s_sum[CDIM];
    __shared__ float s_sq[CDIM];

    const int t    = threadIdx.x;
    const int lane = t & 31;
    const int wid  = t >> 5;
    const int grp  = lane >> 2;
    const int tg   = lane & 3;
    const int m_base = (wid & 1) * 64;
    const int n_base = (wid >> 1) * 32;
    const int a    = blockIdx.y;
    const long i0  = (long)blockIdx.x * 128;
    const uint32_t sbase = smem_u32(smem);

    // producer mapping
    const int pa_row = t >> 1;      // A: row 0..127
    const int pa_kh  = t & 1;       // which 16-k half of the 32-k chunk
    const int pb_k   = t >> 3;      // B: k-row 0..31
    const int pb_nc  = t & 7;       // n-chunk of 16

    if (t < CDIM) { s_sum[t] = 0.f; s_sq[t] = 0.f; }
    {   // gather indices for prev (si=0) / next (si=1)
        int si = t >> 7, r = t & 127;
        long gi = i0 + r;
        int v = NROWS;
        if (gi < NROWS) v = nb[((long)a * 2 + si) * NROWS + gi];
        s_idx[si][r] = v;
    }
    __syncthreads();

    float fa[16], fb[16];

    auto prefetch = [&](int st) {
        const int s = st >> 2, kc = st & 3;
        long gi = i0 + pa_row;
        int ridx;
        if (s == 1) ridx = (gi < NROWS) ? (int)gi : NROWS;
        else        ridx = s_idx[s >> 1][pa_row];
        if (ridx < NROWS) {
            const float* asrc = feat + (long)ridx * CDIM + kc * 32 + pa_kh * 16;
            #pragma unroll
            for (int q = 0; q < 4; q++) {
                float4 v = *(const float4*)(asrc + q * 4);
                fa[q*4+0] = v.x; fa[q*4+1] = v.y; fa[q*4+2] = v.z; fa[q*4+3] = v.w;
            }
        } else {
            #pragma unroll
            for (int q = 0; q < 16; q++) fa[q] = 0.f;
        }
        const float* bsrc = W + ((long)(a * 3 + s) * CDIM + kc * 32 + pb_k) * CDIM + pb_nc * 16;
        #pragma unroll
        for (int q = 0; q < 4; q++) {
            float4 v = *(const float4*)(bsrc + q * 4);
            fb[q*4+0] = v.x; fb[q*4+1] = v.y; fb[q*4+2] = v.z; fb[q*4+3] = v.w;
        }
    };

    auto store_stage = [&](int st) {
        const uint32_t Ab = sbase + (uint32_t)(st & 1) * BUF_SZ;
        const uint32_t Bb = Ab + A_TILE;
        uint32_t h[8];
        #pragma unroll
        for (int q = 0; q < 8; q++) h[q] = pack_h2(fa[2*q], fa[2*q+1]);
        const int swA = (pa_row >> 1) & 3;
        uint32_t a0 = Ab + (uint32_t)pa_row * 64u + (uint32_t)((((pa_kh*2+0) ^ swA)) << 4);
        uint32_t a1 = Ab + (uint32_t)pa_row * 64u + (uint32_t)((((pa_kh*2+1) ^ swA)) << 4);
        STS128(a0, h[0], h[1], h[2], h[3]);
        STS128(a1, h[4], h[5], h[6], h[7]);
        #pragma unroll
        for (int q = 0; q < 8; q++) h[q] = pack_h2(fb[2*q], fb[2*q+1]);
        const int swB = pb_k & 7;
        uint32_t b0 = Bb + (uint32_t)pb_k * 256u + (uint32_t)((((pb_nc*2+0) ^ swB)) << 4);
        uint32_t b1 = Bb + (uint32_t)pb_k * 256u + (uint32_t)((((pb_nc*2+1) ^ swB)) << 4);
        STS128(b0, h[0], h[1], h[2], h[3]);
        STS128(b1, h[4], h[5], h[6], h[7]);
    };

    float acc[4][4][4];
    #pragma unroll
    for (int i = 0; i < 4; i++)
        #pragma unroll
        for (int j = 0; j < 4; j++)
            #pragma unroll
            for (int q = 0; q < 4; q++) acc[i][j][q] = 0.f;

    // ldmatrix lane-address components (constant per thread)
    const int l15 = lane & 15;
    const int lhi = lane >> 4;

    prefetch(0);
    store_stage(0);
    __syncthreads();

    #pragma unroll 1
    for (int st = 0; st < 12; st++) {
        if (st + 1 < 12) prefetch(st + 1);   // LDG in flight over the mma block

        const uint32_t Ab = sbase + (uint32_t)(st & 1) * BUF_SZ;
        const uint32_t Bb = Ab + A_TILE;

        #pragma unroll
        for (int ks = 0; ks < 2; ks++) {     // two k16-steps per 32-k stage
            uint32_t av[4][4];
            #pragma unroll
            for (int mt = 0; mt < 4; mt++) {
                int row = m_base + mt * 16 + l15;
                int ch  = 2 * ks + lhi;
                uint32_t ad = Ab + (uint32_t)row * 64u
                            + (uint32_t)(((ch ^ ((row >> 1) & 3))) << 4);
                LDSM_X4(av[mt], ad);
            }
            uint32_t bv[2][4];
            #pragma unroll
            for (int ntp = 0; ntp < 2; ntp++) {
                int k  = ks * 16 + l15;
                int ch = (n_base >> 3) + ntp * 2 + lhi;
                uint32_t bd = Bb + (uint32_t)k * 256u
                            + (uint32_t)(((ch ^ (k & 7))) << 4);
                LDSM_X4_T(bv[ntp], bd);
            }
            #pragma unroll
            for (int mt = 0; mt < 4; mt++)
                #pragma unroll
                for (int nt = 0; nt < 4; nt++)
                    MMA_F16(acc[mt][nt], av[mt], &bv[nt >> 1][(nt & 1) * 2]);
        }

        if (st + 1 < 12) store_stage(st + 1);
        __syncthreads();
    }

    // ---- store tile to scratch + per-column stats ----
    const int vr = (int)(((NROWS - i0) < 128) ? (NROWS - i0) : 128);
    float* sc = g_scratch + ((long)a * NPAD + i0) * CDIM;

    #pragma unroll
    for (int nt = 0; nt < 4; nt++) {
        const int c_lo = n_base + nt * 8 + tg * 2;
        float sA = 0.f, qA = 0.f, sB = 0.f, qB = 0.f;
        #pragma unroll
        for (int mt = 0; mt < 4; mt++) {
            const int r0 = m_base + mt * 16 + grp;
            const int r1 = r0 + 8;
            float2 v0 = make_float2(acc[mt][nt][0], acc[mt][nt][1]);
            float2 v1 = make_float2(acc[mt][nt][2], acc[mt][nt][3]);
            *(float2*)(sc + (long)r0 * CDIM + c_lo) = v0;
            *(float2*)(sc + (long)r1 * CDIM + c_lo) = v1;
            if (r0 < vr) { sA += v0.x; qA += v0.x * v0.x; sB += v0.y; qB += v0.y * v0.y; }
            if (r1 < vr) { sA += v1.x; qA += v1.x * v1.x; sB += v1.y; qB += v1.y * v1.y; }
        }
        atomicAdd(&s_sum[c_lo],     sA); atomicAdd(&s_sq[c_lo],     qA);
        atomicAdd(&s_sum[c_lo + 1], sB); atomicAdd(&s_sq[c_lo + 1], qB);
    }
    __syncthreads();
    if (t < CDIM) {
        atomicAdd(&g_sum[a * CDIM + t],   s_sum[t]);
        atomicAdd(&g_sumsq[a * CDIM + t], s_sq[t]);
    }
}

__global__ void finalize_kernel(const float* __restrict__ gamma,
                                const float* __restrict__ beta)
{
    int t = blockIdx.x * blockDim.x + threadIdx.x;
    if (t >= 3 * CDIM) return;
    float inv_n = 1.0f / (float)NROWS;
    float mu  = g_sum[t] * inv_n;
    float var = g_sumsq[t] * inv_n - mu * mu;
    float sc  = gamma[t] * rsqrtf(var + EPS);
    g_scale[t] = sc;
    g_shift[t] = beta[t] - mu * sc;
}

__global__ __launch_bounds__(256)
void epilogue_kernel(const float* __restrict__ feat, float* __restrict__ out)
{
    long gid = (long)blockIdx.x * blockDim.x + threadIdx.x;   // one float4 each
    if (gid >= (long)NROWS * (CDIM / 4)) return;
    long i  = gid >> 5;
    int  c4 = ((int)gid & 31) << 2;

    float4 f = *(const float4*)(feat + i * CDIM + c4);
    float r0 = 0.f, r1 = 0.f, r2 = 0.f, r3 = 0.f;
    #pragma unroll
    for (int a = 0; a < 3; a++) {
        float4 v  = *(const float4*)(g_scratch + ((long)a * NPAD + i) * CDIM + c4);
        float4 sc = *(const float4*)(g_scale + a * CDIM + c4);
        float4 sh = *(const float4*)(g_shift + a * CDIM + c4);
        r0 += 1.f / (1.f + __expf(-(v.x * sc.x + sh.x)));
        r1 += 1.f / (1.f + __expf(-(v.y * sc.y + sh.y)));
        r2 += 1.f / (1.f + __expf(-(v.z * sc.z + sh.z)));
        r3 += 1.f / (1.f + __expf(-(v.w * sc.w + sh.w)));
    }
    float4 o = make_float4(r0 * f.x, r1 * f.y, r2 * f.z, r3 * f.w);
    *(float4*)(out + i * CDIM + c4) = o;
}

extern "C" void kernel_launch(void* const* d_in, const int* in_sizes, int n_in,
                              void* d_out, int out_size)
{
    const float* feat  = (const float*)d_in[0];
    const int*   nb    = (const int*)  d_in[1];
    const float* W     = (const float*)d_in[2];
    const float* gamma = (const float*)d_in[3];
    const float* beta  = (const float*)d_in[4];
    float*       out   = (float*)d_out;

    cudaFuncSetAttribute(gemm_bn_stats_kernel,
                         cudaFuncAttributeMaxDynamicSharedMemorySize, SMEM_DYN);

    zero_stats_kernel<<<2, 256>>>();
    dim3 g(NPAD / 128, 3);
    gemm_bn_stats_kernel<<<g, 256, SMEM_DYN>>>(feat, nb, W);
    finalize_kernel<<<2, 256>>>(gamma, beta);
    epilogue_kernel<<<25000, 256>>>(feat, out);
}

// round 10
// speedup vs baseline: 2.8027x; 1.1725x over previous
#include <cuda_runtime.h>
#include <cuda_fp16.h>
#include <cstdint>

#define NROWS 200000
#define NPAD  200064   /* 1563 * 128 */
#define CDIM  128
#define EPS   1e-5f

__device__ __half g_featH[(long)NROWS * CDIM];
__device__ __half g_WH[9 * CDIM * CDIM];
__device__ __half g_scratchH[3L * NPAD * CDIM];
__device__ float  g_sum[3 * CDIM];
__device__ float  g_sumsq[3 * CDIM];
__device__ float  g_scale[3 * CDIM];
__device__ float  g_shift[3 * CDIM];

__device__ __forceinline__ uint32_t smem_u32(const void* p) {
    uint32_t a;
    asm("{ .reg .u64 t; cvta.to.shared.u64 t, %1; cvt.u32.u64 %0, t; }" : "=r"(a) : "l"(p));
    return a;
}

#define STS128(addr, r0, r1, r2, r3) \
    asm volatile("st.shared.v4.b32 [%0], {%1,%2,%3,%4};" \
                 :: "r"(addr), "r"(r0), "r"(r1), "r"(r2), "r"(r3) : "memory")

#define LDSM_X4(r, addr) \
    asm volatile("ldmatrix.sync.aligned.m8n8.x4.shared.b16 {%0,%1,%2,%3}, [%4];" \
                 : "=r"((r)[0]), "=r"((r)[1]), "=r"((r)[2]), "=r"((r)[3]) : "r"(addr))
#define LDSM_X4_T(r, addr) \
    asm volatile("ldmatrix.sync.aligned.m8n8.x4.trans.shared.b16 {%0,%1,%2,%3}, [%4];" \
                 : "=r"((r)[0]), "=r"((r)[1]), "=r"((r)[2]), "=r"((r)[3]) : "r"(addr))

#define MMA_F16(c, au, bu)                                                      \
    asm volatile("mma.sync.aligned.m16n8k16.row.col.f32.f16.f16.f32 "           \
        "{%0,%1,%2,%3}, {%4,%5,%6,%7}, {%8,%9}, {%0,%1,%2,%3};"                 \
        : "+f"((c)[0]), "+f"((c)[1]), "+f"((c)[2]), "+f"((c)[3])                \
        : "r"((au)[0]), "r"((au)[1]), "r"((au)[2]), "r"((au)[3]),               \
          "r"((bu)[0]), "r"((bu)[1]))

// fp16 SMEM tiles per stage: A [128 rows x 32 k] = 64 B/row (4 x 16B chunks,
// chunk ^= (row>>1)&3). B [32 k x 128 n] = 256 B/row (16 chunks, chunk ^= k&7).
#define A_TILE    8192u
#define B_TILE    8192u
#define BUF_SZ    16384u
#define SMEM_DYN  32768u   /* 2 buffers */

__global__ void zero_stats_kernel() {
    int t = blockIdx.x * blockDim.x + threadIdx.x;
    if (t < 3 * CDIM) { g_sum[t] = 0.f; g_sumsq[t] = 0.f; }
}

// fp32 -> fp16 copies: features and W (once per launch)
__global__ __launch_bounds__(256)
void convert_feat_kernel(const float* __restrict__ feat)
{
    long tid = (long)blockIdx.x * blockDim.x + threadIdx.x;   // 8 floats each
    long base = tid * 8;
    if (base >= (long)NROWS * CDIM) return;
    float4 v0 = *(const float4*)(feat + base);
    float4 v1 = *(const float4*)(feat + base + 4);
    __half2 h[4];
    h[0] = __floats2half2_rn(v0.x, v0.y);
    h[1] = __floats2half2_rn(v0.z, v0.w);
    h[2] = __floats2half2_rn(v1.x, v1.y);
    h[3] = __floats2half2_rn(v1.z, v1.w);
    *(uint4*)(g_featH + base) = *(uint4*)h;
}

__global__ __launch_bounds__(256)
void convert_w_kernel(const float* __restrict__ W)
{
    long tid = (long)blockIdx.x * blockDim.x + threadIdx.x;   // 8 floats each
    long base = tid * 8;
    if (base >= 9L * CDIM * CDIM) return;
    float4 v0 = *(const float4*)(W + base);
    float4 v1 = *(const float4*)(W + base + 4);
    __half2 h[4];
    h[0] = __floats2half2_rn(v0.x, v0.y);
    h[1] = __floats2half2_rn(v0.z, v0.w);
    h[2] = __floats2half2_rn(v1.x, v1.y);
    h[3] = __floats2half2_rn(v1.z, v1.w);
    *(uint4*)(g_WH + base) = *(uint4*)h;
}

// One CTA: 128-row x 128-col tile of out_a for axis a = blockIdx.y.
// 8 warps: wm = wid&1 (two 64-row bands), wn = wid>>1 (four 32-col bands).
// Warp tile 64x32 = 4x4 mma(m16n8k16) tiles, fp16 in, fp32 accumulate.
__global__ __launch_bounds__(256, 2)
void gemm_bn_stats_kernel(const int* __restrict__ nb)
{
    extern __shared__ char smem[];
    __shared__ int   s_idx[2][128];
    __shared__ float s_sum[CDIM];
    __shared__ float s_sq[CDIM];

    const int t    = threadIdx.x;
    const int lane = t & 31;
    const int wid  = t >> 5;
    const int grp  = lane >> 2;
    const int tg   = lane & 3;
    const int m_base = (wid & 1) * 64;
    const int n_base = (wid >> 1) * 32;
    const int a    = blockIdx.y;
    const long i0  = (long)blockIdx.x * 128;
    const uint32_t sbase = smem_u32(smem);

    // producer mapping (fp16 source): A thread covers 32 B = 2 chunks
    const int pa_row = t >> 1;      // A: row 0..127
    const int pa_kh  = t & 1;       // 16-half half of the 32-k chunk
    const int pb_k   = t >> 3;      // B: k-row 0..31
    const int pb_nc  = t & 7;       // 16-half n-chunk pair

    if (t < CDIM) { s_sum[t] = 0.f; s_sq[t] = 0.f; }
    {   // gather indices for prev (si=0) / next (si=1)
        int si = t >> 7, r = t & 127;
        long gi = i0 + r;
        int v = NROWS;
        if (gi < NROWS) v = nb[((long)a * 2 + si) * NROWS + gi];
        s_idx[si][r] = v;
    }
    __syncthreads();

    uint4 va0, va1, vb0, vb1;

    auto prefetch = [&](int st) {
        const int s = st >> 2, kc = st & 3;
        long gi = i0 + pa_row;
        int ridx;
        if (s == 1) ridx = (gi < NROWS) ? (int)gi : NROWS;
        else        ridx = s_idx[s >> 1][pa_row];
        if (ridx < NROWS) {
            const __half* asrc = g_featH + (long)ridx * CDIM + kc * 32 + pa_kh * 16;
            va0 = *(const uint4*)asrc;
            va1 = *(const uint4*)(asrc + 8);
        } else {
            va0 = make_uint4(0u, 0u, 0u, 0u);
            va1 = make_uint4(0u, 0u, 0u, 0u);
        }
        const __half* bsrc = g_WH + ((long)(a * 3 + s) * CDIM + kc * 32 + pb_k) * CDIM + pb_nc * 16;
        vb0 = *(const uint4*)bsrc;
        vb1 = *(const uint4*)(bsrc + 8);
    };

    auto store_stage = [&](int st) {
        const uint32_t Ab = sbase + (uint32_t)(st & 1) * BUF_SZ;
        const uint32_t Bb = Ab + A_TILE;
        const int swA = (pa_row >> 1) & 3;
        uint32_t a0 = Ab + (uint32_t)pa_row * 64u + (uint32_t)((((pa_kh*2+0) ^ swA)) << 4);
        uint32_t a1 = Ab + (uint32_t)pa_row * 64u + (uint32_t)((((pa_kh*2+1) ^ swA)) << 4);
        STS128(a0, va0.x, va0.y, va0.z, va0.w);
        STS128(a1, va1.x, va1.y, va1.z, va1.w);
        const int swB = pb_k & 7;
        uint32_t b0 = Bb + (uint32_t)pb_k * 256u + (uint32_t)((((pb_nc*2+0) ^ swB)) << 4);
        uint32_t b1 = Bb + (uint32_t)pb_k * 256u + (uint32_t)((((pb_nc*2+1) ^ swB)) << 4);
        STS128(b0, vb0.x, vb0.y, vb0.z, vb0.w);
        STS128(b1, vb1.x, vb1.y, vb1.z, vb1.w);
    };

    float acc[4][4][4];
    #pragma unroll
    for (int i = 0; i < 4; i++)
        #pragma unroll
        for (int j = 0; j < 4; j++)
            #pragma unroll
            for (int q = 0; q < 4; q++) acc[i][j][q] = 0.f;

    const int l15 = lane & 15;
    const int lhi = lane >> 4;

    prefetch(0);
    store_stage(0);
    __syncthreads();

    #pragma unroll 1
    for (int st = 0; st < 12; st++) {
        if (st + 1 < 12) prefetch(st + 1);   // LDG in flight over the mma block

        const uint32_t Ab = sbase + (uint32_t)(st & 1) * BUF_SZ;
        const uint32_t Bb = Ab + A_TILE;

        #pragma unroll
        for (int ks = 0; ks < 2; ks++) {     // two k16-steps per 32-k stage
            uint32_t av[4][4];
            #pragma unroll
            for (int mt = 0; mt < 4; mt++) {
                int row = m_base + mt * 16 + l15;
                int ch  = 2 * ks + lhi;
                uint32_t ad = Ab + (uint32_t)row * 64u
                            + (uint32_t)(((ch ^ ((row >> 1) & 3))) << 4);
                LDSM_X4(av[mt], ad);
            }
            uint32_t bv[2][4];
            #pragma unroll
            for (int ntp = 0; ntp < 2; ntp++) {
                int k  = ks * 16 + l15;
                int ch = (n_base >> 3) + ntp * 2 + lhi;
                uint32_t bd = Bb + (uint32_t)k * 256u
                            + (uint32_t)(((ch ^ (k & 7))) << 4);
                LDSM_X4_T(bv[ntp], bd);
            }
            #pragma unroll
            for (int mt = 0; mt < 4; mt++)
                #pragma unroll
                for (int nt = 0; nt < 4; nt++)
                    MMA_F16(acc[mt][nt], av[mt], &bv[nt >> 1][(nt & 1) * 2]);
        }

        if (st + 1 < 12) store_stage(st + 1);
        __syncthreads();
    }

    // ---- store tile to fp16 scratch + per-column fp32 stats ----
    const int vr = (int)(((NROWS - i0) < 128) ? (NROWS - i0) : 128);
    __half2* sc2 = (__half2*)(g_scratchH + ((long)a * NPAD + i0) * CDIM);

    #pragma unroll
    for (int nt = 0; nt < 4; nt++) {
        const int c_lo = n_base + nt * 8 + tg * 2;
        float sA = 0.f, qA = 0.f, sB = 0.f, qB = 0.f;
        #pragma unroll
        for (int mt = 0; mt < 4; mt++) {
            const int r0 = m_base + mt * 16 + grp;
            const int r1 = r0 + 8;
            sc2[((long)r0 * CDIM + c_lo) >> 1] = __floats2half2_rn(acc[mt][nt][0], acc[mt][nt][1]);
            sc2[((long)r1 * CDIM + c_lo) >> 1] = __floats2half2_rn(acc[mt][nt][2], acc[mt][nt][3]);
            if (r0 < vr) {
                float x = acc[mt][nt][0], y = acc[mt][nt][1];
                sA += x; qA += x * x; sB += y; qB += y * y;
            }
            if (r1 < vr) {
                float x = acc[mt][nt][2], y = acc[mt][nt][3];
                sA += x; qA += x * x; sB += y; qB += y * y;
            }
        }
        atomicAdd(&s_sum[c_lo],     sA); atomicAdd(&s_sq[c_lo],     qA);
        atomicAdd(&s_sum[c_lo + 1], sB); atomicAdd(&s_sq[c_lo + 1], qB);
    }
    __syncthreads();
    if (t < CDIM) {
        atomicAdd(&g_sum[a * CDIM + t],   s_sum[t]);
        atomicAdd(&g_sumsq[a * CDIM + t], s_sq[t]);
    }
}

__global__ void finalize_kernel(const float* __restrict__ gamma,
                                const float* __restrict__ beta)
{
    int t = blockIdx.x * blockDim.x + threadIdx.x;
    if (t >= 3 * CDIM) return;
    float inv_n = 1.0f / (float)NROWS;
    float mu  = g_sum[t] * inv_n;
    float var = g_sumsq[t] * inv_n - mu * mu;
    float sc  = gamma[t] * rsqrtf(var + EPS);
    g_scale[t] = sc;
    g_shift[t] = beta[t] - mu * sc;
}

__global__ __launch_bounds__(256)
void epilogue_kernel(const float* __restrict__ feat, float* __restrict__ out)
{
    long gid = (long)blockIdx.x * blockDim.x + threadIdx.x;   // one float4 each
    if (gid >= (long)NROWS * (CDIM / 4)) return;
    long i  = gid >> 5;
    int  c4 = ((int)gid & 31) << 2;

    float4 f = *(const float4*)(feat + i * CDIM + c4);
    float r0 = 0.f, r1 = 0.f, r2 = 0.f, r3 = 0.f;
    #pragma unroll
    for (int a = 0; a < 3; a++) {
        const __half2* sp = (const __half2*)(g_scratchH + ((long)a * NPAD + i) * CDIM + c4);
        float2 p0 = __half22float2(sp[0]);
        float2 p1 = __half22float2(sp[1]);
        float4 sc = *(const float4*)(g_scale + a * CDIM + c4);
        float4 sh = *(const float4*)(g_shift + a * CDIM + c4);
        r0 += 1.f / (1.f + __expf(-(p0.x * sc.x + sh.x)));
        r1 += 1.f / (1.f + __expf(-(p0.y * sc.y + sh.y)));
        r2 += 1.f / (1.f + __expf(-(p1.x * sc.z + sh.z)));
        r3 += 1.f / (1.f + __expf(-(p1.y * sc.w + sh.w)));
    }
    float4 o = make_float4(r0 * f.x, r1 * f.y, r2 * f.z, r3 * f.w);
    *(float4*)(out + i * CDIM + c4) = o;
}

extern "C" void kernel_launch(void* const* d_in, const int* in_sizes, int n_in,
                              void* d_out, int out_size)
{
    const float* feat  = (const float*)d_in[0];
    const int*   nb    = (const int*)  d_in[1];
    const float* W     = (const float*)d_in[2];
    const float* gamma = (const float*)d_in[3];
    const float* beta  = (const float*)d_in[4];
    float*       out   = (float*)d_out;

    cudaFuncSetAttribute(gemm_bn_stats_kernel,
                         cudaFuncAttributeMaxDynamicSharedMemorySize, SMEM_DYN);

    zero_stats_kernel<<<2, 256>>>();
    convert_feat_kernel<<<12500, 256>>>(feat);
    convert_w_kernel<<<72, 256>>>(W);
    dim3 g(NPAD / 128, 3);
    gemm_bn_stats_kernel<<<g, 256, SMEM_DYN>>>(nb);
    finalize_kernel<<<2, 256>>>(gamma, beta);
    epilogue_kernel<<<25000, 256>>>(feat, out);
}